// round 2
// baseline (speedup 1.0000x reference)
#include <cuda_runtime.h>
#include <cuda_bf16.h>

// MultitaskReadout: y[b,t,:] = concat of per-decoder Linear outputs, masked by
// decoder_index[b,t]. x[16,4096,1024] f32, dims {2,2,30}, out [16,4096,34] f32.
//
//   K0: zero d_out (poisoned 0xAA) + reset compaction counters
//   K1: compact token indices into 3 per-decoder lists
//   K2: warp processes 4 same-decoder tokens; x in registers (32 f32/lane/token,
//       streaming .cs loads), W rows via .nc loads (L1-resident), packed
//       fma.rn.f32x2 accumulation (halves FFMA issue), batched butterfly
//       reduction, scatter active channels only.

#define NTOK   65536      // B*T
#define DIM    1024
#define G      4          // tokens per warp
#define OUTC   34         // 2 + 2 + 30

typedef unsigned long long u64;

__device__ int g_list[3 * NTOK];
__device__ int g_cnt[3];

// ---- packed-pair helpers ---------------------------------------------------
__device__ __forceinline__ void ld_x_cs(const float* p, u64& a, u64& b) {
    // streaming (evict-first): don't thrash W out of L1
    asm volatile("ld.global.cs.v2.b64 {%0,%1}, [%2];" : "=l"(a), "=l"(b) : "l"(p));
}
__device__ __forceinline__ void ld_w_nc(const float* p, u64& a, u64& b) {
    // read-only, L1-cached
    asm("ld.global.nc.v2.b64 {%0,%1}, [%2];" : "=l"(a), "=l"(b) : "l"(p));
}
__device__ __forceinline__ void fma2(u64& acc, u64 a, u64 b) {
    asm("fma.rn.f32x2 %0, %1, %2, %0;" : "+l"(acc) : "l"(a), "l"(b));
}
__device__ __forceinline__ float pair_sum(u64 v) {
    float lo, hi;
    asm("mov.b64 {%0,%1}, %2;" : "=f"(lo), "=f"(hi) : "l"(v));
    return lo + hi;
}

// ---------------------------------------------------------------------------
__global__ void k_zero(float4* __restrict__ out4, int n4) {
    int i = blockIdx.x * blockDim.x + threadIdx.x;
    const float4 z = make_float4(0.f, 0.f, 0.f, 0.f);
    for (; i < n4; i += gridDim.x * blockDim.x) out4[i] = z;
    if (blockIdx.x == 0 && threadIdx.x < 3) g_cnt[threadIdx.x] = 0;
}

// ---------------------------------------------------------------------------
__global__ void k_compact(const int* __restrict__ didx) {
    __shared__ int s_cnt[3];
    __shared__ int s_base[3];
    int t = threadIdx.x;
    if (t < 3) s_cnt[t] = 0;
    __syncthreads();

    int i = blockIdx.x * blockDim.x + t;   // grid sized exactly NTOK/256
    int d = didx[i];
    int lp = atomicAdd(&s_cnt[d], 1);
    __syncthreads();

    if (t < 3) s_base[t] = atomicAdd(&g_cnt[t], s_cnt[t]);
    __syncthreads();

    g_list[d * NTOK + s_base[d] + lp] = i;
}

// ---------------------------------------------------------------------------
__global__ void __launch_bounds__(128)
k_readout(const float* __restrict__ x,
          const float* __restrict__ W0, const float* __restrict__ b0,
          const float* __restrict__ W1, const float* __restrict__ b1,
          const float* __restrict__ W2, const float* __restrict__ b2,
          float* __restrict__ out) {
    const int lane = threadIdx.x & 31;
    const int wg   = (blockIdx.x * blockDim.x + threadIdx.x) >> 5;  // global warp id

    const int c0 = g_cnt[0], c1 = g_cnt[1], c2 = g_cnt[2];
    const int ng0 = (c0 + G - 1) / G;
    const int ng1 = (c1 + G - 1) / G;
    const int ng2 = (c2 + G - 1) / G;

    int d, slot, n;
    if (wg < ng0)                  { d = 0; slot = wg;             n = c0; }
    else if (wg < ng0 + ng1)       { d = 1; slot = wg - ng0;       n = c1; }
    else if (wg < ng0 + ng1 + ng2) { d = 2; slot = wg - ng0 - ng1; n = c2; }
    else return;

    const int* list = g_list + d * NTOK;
    const int  base = slot * G;
    const int  nvalid = min(G, n - base);

    int tok[G];
#pragma unroll
    for (int t = 0; t < G; t++) tok[t] = list[base + min(t, nvalid - 1)];

    // x rows in registers: lane covers elements 4*lane + 128*j (+0..3), j=0..7
    // stored as packed f32x2 pairs for fma.rn.f32x2
    u64 xr[G][8][2];
#pragma unroll
    for (int t = 0; t < G; t++) {
        const float* xp = x + (size_t)tok[t] * DIM + lane * 4;
#pragma unroll
        for (int j = 0; j < 8; j++)
            ld_x_cs(xp + j * 128, xr[t][j][0], xr[t][j][1]);
    }

    const float* W; const float* bb; int rows, off;
    if (d == 0)      { W = W0; bb = b0; rows = 2;  off = 0; }
    else if (d == 1) { W = W1; bb = b1; rows = 2;  off = 2; }
    else             { W = W2; bb = b2; rows = 30; off = 4; }

    for (int r = 0; r < rows; r++) {
        const float* wp = W + (size_t)r * DIM + lane * 4;
        u64 acc0 = 0ull, acc1 = 0ull, acc2 = 0ull, acc3 = 0ull;
#pragma unroll
        for (int j = 0; j < 8; j++) {
            u64 wa, wb;
            ld_w_nc(wp + j * 128, wa, wb);
            fma2(acc0, wa, xr[0][j][0]); fma2(acc0, wb, xr[0][j][1]);
            fma2(acc1, wa, xr[1][j][0]); fma2(acc1, wb, xr[1][j][1]);
            fma2(acc2, wa, xr[2][j][0]); fma2(acc2, wb, xr[2][j][1]);
            fma2(acc3, wa, xr[3][j][0]); fma2(acc3, wb, xr[3][j][1]);
        }
        float s0 = pair_sum(acc0), s1 = pair_sum(acc1);
        float s2 = pair_sum(acc2), s3 = pair_sum(acc3);
        // batched butterfly reduction (4 independent chains)
#pragma unroll
        for (int s = 16; s > 0; s >>= 1) {
            s0 += __shfl_down_sync(0xFFFFFFFFu, s0, s);
            s1 += __shfl_down_sync(0xFFFFFFFFu, s1, s);
            s2 += __shfl_down_sync(0xFFFFFFFFu, s2, s);
            s3 += __shfl_down_sync(0xFFFFFFFFu, s3, s);
        }
        if (lane == 0) {
            const float bv = __ldg(bb + r);
            float a[G] = {s0, s1, s2, s3};
#pragma unroll
            for (int t = 0; t < G; t++)
                if (t < nvalid)
                    out[(size_t)tok[t] * OUTC + off + r] = a[t] + bv;
        }
    }
}

// ---------------------------------------------------------------------------
extern "C" void kernel_launch(void* const* d_in, const int* in_sizes, int n_in,
                              void* d_out, int out_size) {
    const float* x    = (const float*)d_in[0];
    const int*   didx = (const int*)  d_in[1];
    const float* W0   = (const float*)d_in[2];
    const float* b0   = (const float*)d_in[3];
    const float* W1   = (const float*)d_in[4];
    const float* b1   = (const float*)d_in[5];
    const float* W2   = (const float*)d_in[6];
    const float* b2   = (const float*)d_in[7];
    float* out = (float*)d_out;

    // K0: zero output (NTOK*34 floats, divisible by 4) + reset counters
    const int n4 = NTOK * OUTC / 4;             // 557056
    k_zero<<<2176, 256>>>(reinterpret_cast<float4*>(out), n4);

    // K1: compaction (exactly NTOK threads)
    k_compact<<<NTOK / 256, 256>>>(didx);

    // K2: main readout. Worst-case groups = ceil(NTOK/G)+2; 4 warps/block.
    const int max_groups = (NTOK + G - 1) / G + 2;          // 16386
    const int nblocks = (max_groups + 3) / 4;               // 4097
    k_readout<<<nblocks, 128>>>(x, W0, b0, W1, b1, W2, b2, out);
}